// round 1
// baseline (speedup 1.0000x reference)
#include <cuda_runtime.h>
#include <cstdint>
#include <cstddef>

// ---------------- problem constants (match reference_code) ----------------
static constexpr int E_EDGES = 131072;   // edges
static constexpr int T_TRIP  = 1048576;  // triplets
static constexpr int H_DIM   = 256;      // hidden
static constexpr int I_DIM   = 64;       // int_emb_size
static constexpr int NR      = 6;        // num_radial
static constexpr int NSR     = 42;       // num_spherical * num_radial
static constexpr int BAS     = 8;        // basis_emb_size

// ---------------- scratch (static device memory; no allocation) -----------
__device__ float g_xji [(size_t)E_EDGES * H_DIM];   // 134 MB
__device__ float g_bufA[(size_t)E_EDGES * H_DIM];   // 134 MB
__device__ float g_bufB[(size_t)E_EDGES * H_DIM];   // 134 MB
__device__ float g_xkjd[(size_t)E_EDGES * I_DIM];   // 32 MB
__device__ float g_agg [(size_t)E_EDGES * I_DIM];   // 32 MB

// ---------------- helpers ----------------
__device__ __forceinline__ float silu_f(float v) {
    return v * (1.0f / (1.0f + __expf(-v)));
}

__device__ __forceinline__ unsigned long long pack2(float lo, float hi) {
    unsigned long long r;
    asm("mov.b64 %0, {%1, %2};" : "=l"(r) : "f"(lo), "f"(hi));
    return r;
}
__device__ __forceinline__ void unpack2(unsigned long long v, float& lo, float& hi) {
    asm("mov.b64 {%0, %1}, %2;" : "=f"(lo), "=f"(hi) : "l"(v));
}
// packed dual-FMA: d = a * b + d   (per 32-bit half), Blackwell f32x2 pipe
__device__ __forceinline__ void fma2(unsigned long long& d, unsigned long long a,
                                     unsigned long long b) {
    asm("fma.rn.f32x2 %0, %1, %2, %3;" : "=l"(d) : "l"(a), "l"(b), "l"(d));
}

// ---------------- fused GEMM:  C = [res +] silu(A @ W [+ bias]) ----------------
// A: [M,K] row-major, W: [K,N] row-major, res/C: [M,N]
template <int BM, int BN, int BK, int TM, int TN>
__global__ __launch_bounds__((BM / TM) * (BN / TN))
void gemm_silu_kernel(const float* __restrict__ A,
                      const float* __restrict__ W,
                      const float* __restrict__ bias,   // nullable
                      const float* __restrict__ res,    // nullable
                      float* __restrict__ C,
                      int M, int N, int K)
{
    constexpr int THREADS = (BM / TM) * (BN / TN);
    __shared__ __align__(16) float As[BK][BM];
    __shared__ __align__(16) float Ws[BK][BN];

    const int tid = threadIdx.x;
    const int tx  = tid % (BN / TN);
    const int ty  = tid / (BN / TN);
    const int block_row = blockIdx.x * BM;
    const int block_col = blockIdx.y * BN;

    unsigned long long acc[TM][TN / 2];
#pragma unroll
    for (int i = 0; i < TM; i++)
#pragma unroll
        for (int j = 0; j < TN / 2; j++) acc[i][j] = 0ull;

    for (int k0 = 0; k0 < K; k0 += BK) {
        // load A tile [BM x BK], store transposed As[k][m]
#pragma unroll
        for (int i = tid; i < BM * BK / 4; i += THREADS) {
            int m  = i / (BK / 4);
            int kv = i % (BK / 4);
            float4 v = *reinterpret_cast<const float4*>(
                &A[(size_t)(block_row + m) * K + k0 + kv * 4]);
            As[kv * 4 + 0][m] = v.x;
            As[kv * 4 + 1][m] = v.y;
            As[kv * 4 + 2][m] = v.z;
            As[kv * 4 + 3][m] = v.w;
        }
        // load W tile [BK x BN]
#pragma unroll
        for (int i = tid; i < BK * BN / 4; i += THREADS) {
            int k  = i / (BN / 4);
            int nv = i % (BN / 4);
            *reinterpret_cast<float4*>(&Ws[k][nv * 4]) =
                *reinterpret_cast<const float4*>(
                    &W[(size_t)(k0 + k) * N + block_col + nv * 4]);
        }
        __syncthreads();

#pragma unroll
        for (int k = 0; k < BK; k++) {
            float a[TM];
#pragma unroll
            for (int i = 0; i < TM; i += 4) {
                float4 v = *reinterpret_cast<const float4*>(&As[k][ty * TM + i]);
                a[i] = v.x; a[i + 1] = v.y; a[i + 2] = v.z; a[i + 3] = v.w;
            }
            unsigned long long bb[TN / 2];
#pragma unroll
            for (int j = 0; j < TN; j += 4) {
                float4 v = *reinterpret_cast<const float4*>(&Ws[k][tx * TN + j]);
                bb[j / 2]     = pack2(v.x, v.y);
                bb[j / 2 + 1] = pack2(v.z, v.w);
            }
#pragma unroll
            for (int i = 0; i < TM; i++) {
                unsigned long long ap = pack2(a[i], a[i]);
#pragma unroll
                for (int j = 0; j < TN / 2; j++) fma2(acc[i][j], ap, bb[j]);
            }
        }
        __syncthreads();
    }

    // epilogue: bias -> silu -> +res -> store
#pragma unroll
    for (int i = 0; i < TM; i++) {
        int row = block_row + ty * TM + i;
#pragma unroll
        for (int j = 0; j < TN / 2; j++) {
            float v0, v1;
            unpack2(acc[i][j], v0, v1);
            int col = block_col + tx * TN + j * 2;
            if (bias) { v0 += bias[col]; v1 += bias[col + 1]; }
            v0 = silu_f(v0);
            v1 = silu_f(v1);
            if (res) {
                float2 r = *reinterpret_cast<const float2*>(
                    &res[(size_t)row * N + col]);
                v0 += r.x; v1 += r.y;
            }
            float2 o; o.x = v0; o.y = v1;
            *reinterpret_cast<float2*>(&C[(size_t)row * N + col]) = o;
        }
    }
}

// ---------------- rbf gating: xkj[r,:] *= (rbf[r,:] @ W1) @ W2 ----------------
__global__ void rbf_gate_kernel(float* __restrict__ xkj,
                                const float* __restrict__ rbf,
                                const float* __restrict__ W1,   // [6,8]
                                const float* __restrict__ W2)   // [8,256]
{
    __shared__ __align__(16) float sW2[BAS * H_DIM];  // 8 KB
    __shared__ float sW1[NR * BAS];                   // 48 floats
    for (int i = threadIdx.x; i < BAS * H_DIM; i += blockDim.x) sW2[i] = W2[i];
    for (int i = threadIdx.x; i < NR * BAS; i += blockDim.x)    sW1[i] = W1[i];
    __syncthreads();

    const int lane  = threadIdx.x & 31;
    const int wglob = (blockIdx.x * blockDim.x + threadIdx.x) >> 5;
    const int nwarp = (gridDim.x * blockDim.x) >> 5;
    const int j = lane & 7;
    const int g = lane >> 3;   // 0..3

    for (int r = wglob; r < E_EDGES; r += nwarp) {
        float s = 0.f;
        for (int i = g; i < NR; i += 4) s += rbf[(size_t)r * NR + i] * sW1[i * BAS + j];
        s += __shfl_xor_sync(0xffffffffu, s, 8);
        s += __shfl_xor_sync(0xffffffffu, s, 16);
        // each lane handles 8 contiguous cols
        int c = lane * 8;
        float4 g0 = make_float4(0, 0, 0, 0), g1 = make_float4(0, 0, 0, 0);
#pragma unroll
        for (int jj = 0; jj < BAS; jj++) {
            float sj = __shfl_sync(0xffffffffu, s, jj);
            float4 w0 = *reinterpret_cast<const float4*>(&sW2[jj * H_DIM + c]);
            float4 w1 = *reinterpret_cast<const float4*>(&sW2[jj * H_DIM + c + 4]);
            g0.x += sj * w0.x; g0.y += sj * w0.y; g0.z += sj * w0.z; g0.w += sj * w0.w;
            g1.x += sj * w1.x; g1.y += sj * w1.y; g1.z += sj * w1.z; g1.w += sj * w1.w;
        }
        float4* p0 = reinterpret_cast<float4*>(&xkj[(size_t)r * H_DIM + c]);
        float4* p1 = reinterpret_cast<float4*>(&xkj[(size_t)r * H_DIM + c + 4]);
        float4 x0 = *p0, x1 = *p1;
        x0.x *= g0.x; x0.y *= g0.y; x0.z *= g0.z; x0.w *= g0.w;
        x1.x *= g1.x; x1.y *= g1.y; x1.z *= g1.z; x1.w *= g1.w;
        *p0 = x0; *p1 = x1;
    }
}

// ---------------- zero scratch ----------------
__global__ void zero_kernel(float4* __restrict__ p, int n4)
{
    int i = blockIdx.x * blockDim.x + threadIdx.x;
    int stride = gridDim.x * blockDim.x;
    for (; i < n4; i += stride) p[i] = make_float4(0, 0, 0, 0);
}

// ---------------- triplet pass: s = (sbf@W1)@W2; m = xkjd[idx_kj]*s; agg[idx_ji]+=m
// half-warp (16 lanes) per triplet, float4 vector atomics.
__global__ void triplet_kernel(const float* __restrict__ sbf,
                               const int* __restrict__ idx_kj,
                               const int* __restrict__ idx_ji,
                               const float* __restrict__ W1,   // [42,8]
                               const float* __restrict__ W2,   // [8,64]
                               const float* __restrict__ xkjd, // [E,64]
                               float* __restrict__ agg)        // [E,64]
{
    __shared__ float sW1[NSR * BAS];                 // 336
    __shared__ __align__(16) float sW2[BAS * I_DIM]; // 512
    for (int i = threadIdx.x; i < NSR * BAS; i += blockDim.x) sW1[i] = W1[i];
    for (int i = threadIdx.x; i < BAS * I_DIM; i += blockDim.x) sW2[i] = W2[i];
    __syncthreads();

    const int lane  = threadIdx.x & 31;
    const int wglob = (blockIdx.x * blockDim.x + threadIdx.x) >> 5;
    const int nwarp = (gridDim.x * blockDim.x) >> 5;
    const int sub = lane >> 4;   // which triplet of the pair
    const int sl  = lane & 15;
    const int j   = sl & 7;
    const int g   = sl >> 3;     // 0..1

    for (int p = wglob; p * 2 < T_TRIP; p += nwarp) {
        int t = p * 2 + sub;
        const float* srow = sbf + (size_t)t * NSR;
        // s8[j] = sum_i sbf[t,i] * W1[i,j]  (split i over 2 lane groups)
        float s = 0.f;
        for (int i = g; i < NSR; i += 2) s += srow[i] * sW1[i * BAS + j];
        s += __shfl_xor_sync(0xffffffffu, s, 8);

        int ekj = idx_kj[t];
        int eji = idx_ji[t];
        int c = sl * 4;  // 16 lanes x 4 cols = 64
        float4 xv = *reinterpret_cast<const float4*>(&xkjd[(size_t)ekj * I_DIM + c]);
        float4 m = make_float4(0, 0, 0, 0);
#pragma unroll
        for (int jj = 0; jj < BAS; jj++) {
            float sj = __shfl_sync(0xffffffffu, s, (sub << 4) + jj);
            float4 w = *reinterpret_cast<const float4*>(&sW2[jj * I_DIM + c]);
            m.x += sj * w.x; m.y += sj * w.y; m.z += sj * w.z; m.w += sj * w.w;
        }
        m.x *= xv.x; m.y *= xv.y; m.z *= xv.z; m.w *= xv.w;
        atomicAdd(reinterpret_cast<float4*>(&agg[(size_t)eji * I_DIM + c]), m);
    }
}

// ---------------- launch ----------------
extern "C" void kernel_launch(void* const* d_in, const int* in_sizes, int n_in,
                              void* d_out, int out_size)
{
    const float* x      = (const float*)d_in[0];
    const float* rbf    = (const float*)d_in[1];
    const float* sbf    = (const float*)d_in[2];
    const int*   idx_kj = (const int*)d_in[3];
    const int*   idx_ji = (const int*)d_in[4];
    const float* W_ji   = (const float*)d_in[5];
    const float* b_ji   = (const float*)d_in[6];
    const float* W_kj   = (const float*)d_in[7];
    const float* b_kj   = (const float*)d_in[8];
    const float* W_rbf1 = (const float*)d_in[9];
    const float* W_rbf2 = (const float*)d_in[10];
    const float* W_sbf1 = (const float*)d_in[11];
    const float* W_sbf2 = (const float*)d_in[12];
    const float* W_down = (const float*)d_in[13];
    const float* W_up   = (const float*)d_in[14];
    const float* Wb1_1  = (const float*)d_in[15];
    const float* bb1_1  = (const float*)d_in[16];
    const float* Wb1_2  = (const float*)d_in[17];
    const float* bb1_2  = (const float*)d_in[18];
    const float* W_lin  = (const float*)d_in[19];
    const float* b_lin  = (const float*)d_in[20];
    const float* Wa1_1  = (const float*)d_in[21];
    const float* ba1_1  = (const float*)d_in[22];
    const float* Wa1_2  = (const float*)d_in[23];
    const float* ba1_2  = (const float*)d_in[24];
    const float* Wa2_1  = (const float*)d_in[25];
    const float* ba2_1  = (const float*)d_in[26];
    const float* Wa2_2  = (const float*)d_in[27];
    const float* ba2_2  = (const float*)d_in[28];
    float* out = (float*)d_out;

    float *xji, *bufA, *bufB, *xkjd, *agg;
    cudaGetSymbolAddress((void**)&xji,  g_xji);
    cudaGetSymbolAddress((void**)&bufA, g_bufA);
    cudaGetSymbolAddress((void**)&bufB, g_bufB);
    cudaGetSymbolAddress((void**)&xkjd, g_xkjd);
    cudaGetSymbolAddress((void**)&agg,  g_agg);

    const dim3 gBig(E_EDGES / 128, H_DIM / 128);   // (1024, 2)
    const dim3 gDown(E_EDGES / 128, 1);

    // edge-wise transforms
    gemm_silu_kernel<128, 128, 16, 8, 8><<<gBig, 256>>>(
        x, W_ji, b_ji, nullptr, xji, E_EDGES, H_DIM, H_DIM);
    gemm_silu_kernel<128, 128, 16, 8, 8><<<gBig, 256>>>(
        x, W_kj, b_kj, nullptr, bufA, E_EDGES, H_DIM, H_DIM);
    rbf_gate_kernel<<<2048, 256>>>(bufA, rbf, W_rbf1, W_rbf2);
    gemm_silu_kernel<128, 64, 16, 8, 4><<<gDown, 256>>>(
        bufA, W_down, nullptr, nullptr, xkjd, E_EDGES, I_DIM, H_DIM);

    // triplet message passing
    zero_kernel<<<1024, 256>>>((float4*)agg, E_EDGES * I_DIM / 4);
    triplet_kernel<<<2048, 256>>>(sbf, idx_kj, idx_ji, W_sbf1, W_sbf2, xkjd, agg);

    // up-projection + x_ji residual:  h = x_ji + silu(agg @ W_up)
    gemm_silu_kernel<128, 128, 16, 8, 8><<<gBig, 256>>>(
        agg, W_up, nullptr, xji, bufA, E_EDGES, H_DIM, I_DIM);

    // pre-skip residual block: h = h + silu(silu(h@Wb1_1+b)@Wb1_2+b)
    gemm_silu_kernel<128, 128, 16, 8, 8><<<gBig, 256>>>(
        bufA, Wb1_1, bb1_1, nullptr, bufB, E_EDGES, H_DIM, H_DIM);
    gemm_silu_kernel<128, 128, 16, 8, 8><<<gBig, 256>>>(
        bufB, Wb1_2, bb1_2, bufA, bufA, E_EDGES, H_DIM, H_DIM);

    // skip: h = silu(h@W_lin+b) + x
    gemm_silu_kernel<128, 128, 16, 8, 8><<<gBig, 256>>>(
        bufA, W_lin, b_lin, x, bufB, E_EDGES, H_DIM, H_DIM);

    // post-skip residual block 1
    gemm_silu_kernel<128, 128, 16, 8, 8><<<gBig, 256>>>(
        bufB, Wa1_1, ba1_1, nullptr, bufA, E_EDGES, H_DIM, H_DIM);
    gemm_silu_kernel<128, 128, 16, 8, 8><<<gBig, 256>>>(
        bufA, Wa1_2, ba1_2, bufB, bufB, E_EDGES, H_DIM, H_DIM);

    // post-skip residual block 2 -> final output
    gemm_silu_kernel<128, 128, 16, 8, 8><<<gBig, 256>>>(
        bufB, Wa2_1, ba2_1, nullptr, bufA, E_EDGES, H_DIM, H_DIM);
    gemm_silu_kernel<128, 128, 16, 8, 8><<<gBig, 256>>>(
        bufA, Wa2_2, ba2_2, bufB, out, E_EDGES, H_DIM, H_DIM);
}

// round 4
// speedup vs baseline: 1.9421x; 1.9421x over previous
#include <cuda_runtime.h>
#include <cstdint>
#include <cstddef>

// ---------------- problem constants ----------------
static constexpr int E_EDGES = 131072;
static constexpr int T_TRIP  = 1048576;
static constexpr int H_DIM   = 256;
static constexpr int I_DIM   = 64;
static constexpr int NR      = 6;
static constexpr int NSR     = 42;
static constexpr int BAS     = 8;

// ---------------- scratch (static device memory) ----------------
__device__ float g_xr  [(size_t)E_EDGES * H_DIM];
__device__ float g_xji [(size_t)E_EDGES * H_DIM];
__device__ float g_bufA[(size_t)E_EDGES * H_DIM];
__device__ float g_bufB[(size_t)E_EDGES * H_DIM];
__device__ float g_xkjd[(size_t)E_EDGES * I_DIM];
__device__ float g_agg [(size_t)E_EDGES * I_DIM];
__device__ float g_wr  [622592];   // tf32-rounded weights, concatenated

// weight offsets inside g_wr
static constexpr int WO_JI   = 0;
static constexpr int WO_KJ   = 65536;
static constexpr int WO_B11  = 131072;
static constexpr int WO_B12  = 196608;
static constexpr int WO_LIN  = 262144;
static constexpr int WO_A11  = 327680;
static constexpr int WO_A12  = 393216;
static constexpr int WO_A21  = 458752;
static constexpr int WO_A22  = 524288;
static constexpr int WO_DOWN = 589824;   // 256*64
static constexpr int WO_UP   = 606208;   // 64*256

// ---------------- helpers ----------------
__device__ __forceinline__ uint32_t smem_to_u32(const void* p) {
    uint32_t a;
    asm("{ .reg .u64 t; cvta.to.shared.u64 t, %1; cvt.u32.u64 %0, t; }" : "=r"(a) : "l"(p));
    return a;
}
__device__ __forceinline__ uint32_t tf32r(float v) {
    uint32_t o; asm("cvt.rna.tf32.f32 %0, %1;" : "=r"(o) : "f"(v)); return o;
}
__device__ __forceinline__ float silu_f(float v) {
    return v * (1.0f / (1.0f + __expf(-v)));
}
__device__ __forceinline__ void cp_async16(uint32_t dst, const void* src) {
    asm volatile("cp.async.cg.shared.global [%0], [%1], 16;" :: "r"(dst), "l"(src));
}
__device__ __forceinline__ void mma_tf32(float d[4], const uint32_t a[4], const uint32_t b[2]) {
    asm volatile(
        "mma.sync.aligned.m16n8k8.row.col.f32.tf32.tf32.f32 "
        "{%0,%1,%2,%3}, {%4,%5,%6,%7}, {%8,%9}, {%0,%1,%2,%3};"
        : "+f"(d[0]), "+f"(d[1]), "+f"(d[2]), "+f"(d[3])
        : "r"(a[0]), "r"(a[1]), "r"(a[2]), "r"(a[3]), "r"(b[0]), "r"(b[1]));
}

// ============ mma.sync tf32 GEMM: C = [res +] silu(A @ W [+ bias]) ============
// A: [M, K] row-major fp32 (tf32-pre-rounded preferred)
// W: [K, Nfull] row-major fp32 (tf32-pre-rounded)
// Block tile: 128 x BN x 16, 8 warps (4 in M x 2 in N), warp tile 32 x BN/2.
template <int BN, int K>
__global__ void __launch_bounds__(256, 2)
mma_gemm(const float* __restrict__ A, const float* __restrict__ W,
         const float* __restrict__ bias, const float* __restrict__ res,
         float* __restrict__ C, int Nfull)
{
    constexpr int BM = 128, BK = 16, DEPTH = 3;
    constexpr int KT = K / BK;
    constexpr int AS_STRIDE = BK + 4;                 // 20 floats (conflict-free frags)
    constexpr int AS_STAGE  = BM * AS_STRIDE;         // 2560 floats
    constexpr int BS_STRIDE = BN + 4;
    constexpr int BS_STAGE  = BK * BS_STRIDE;
    constexpr int NF = BN / 16;                       // N-frags per warp

    extern __shared__ float smf[];
    float* As = smf;
    float* Bs = smf + DEPTH * AS_STAGE;
    const uint32_t smemA = smem_to_u32(As);
    const uint32_t smemB = smem_to_u32(Bs);

    const int tid = threadIdx.x, lane = tid & 31, wid = tid >> 5;
    const int warpM = wid >> 1, warpN = wid & 1;
    const int row0 = blockIdx.x * BM;
    const int col0 = blockIdx.y * BN;
    const int g = lane >> 2, q = lane & 3;

    float acc[2][NF][4];
#pragma unroll
    for (int mf = 0; mf < 2; mf++)
#pragma unroll
        for (int nf = 0; nf < NF; nf++)
#pragma unroll
            for (int v = 0; v < 4; v++) acc[mf][nf][v] = 0.0f;

    auto load_stage = [&](int s, int kt) {
        const int k0 = kt * BK;
        // A tile: BM x BK = 512 x 16B chunks
#pragma unroll
        for (int i = 0; i < 2; i++) {
            int id = tid + i * 256;
            int m = id >> 2, c4 = (id & 3) * 4;
            uint32_t dst = smemA + (uint32_t)(s * AS_STAGE + m * AS_STRIDE + c4) * 4;
            cp_async16(dst, A + (size_t)(row0 + m) * K + k0 + c4);
        }
        // B tile: BK x BN
        constexpr int BCH = BK * BN / 4;      // 512 (BN=128) or 256 (BN=64)
#pragma unroll
        for (int i = 0; i < BCH / 256; i++) {
            int id = tid + i * 256;
            int k = id / (BN / 4), n4 = (id % (BN / 4)) * 4;
            uint32_t dst = smemB + (uint32_t)(s * BS_STAGE + k * BS_STRIDE + n4) * 4;
            cp_async16(dst, W + (size_t)(k0 + k) * Nfull + col0 + n4);
        }
    };

    // prologue
#pragma unroll
    for (int s = 0; s < DEPTH - 1; s++) {
        load_stage(s, s);
        asm volatile("cp.async.commit_group;" ::: "memory");
    }

    for (int it = 0; it < KT; it++) {
        asm volatile("cp.async.wait_group %0;" :: "n"(DEPTH - 2) : "memory");
        __syncthreads();
        const int nx = it + DEPTH - 1;
        if (nx < KT) load_stage(nx % DEPTH, nx);
        asm volatile("cp.async.commit_group;" ::: "memory");

        const int s = it % DEPTH;
        const float* Asb = As + s * AS_STAGE;
        const float* Bsb = Bs + s * BS_STAGE;
#pragma unroll
        for (int ks = 0; ks < 2; ks++) {
            uint32_t af[2][4];
            uint32_t bf[NF][2];
#pragma unroll
            for (int mf = 0; mf < 2; mf++) {
                int r = warpM * 32 + mf * 16 + g;
                af[mf][0] = __float_as_uint(Asb[r * AS_STRIDE + ks * 8 + q]);
                af[mf][1] = __float_as_uint(Asb[(r + 8) * AS_STRIDE + ks * 8 + q]);
                af[mf][2] = __float_as_uint(Asb[r * AS_STRIDE + ks * 8 + q + 4]);
                af[mf][3] = __float_as_uint(Asb[(r + 8) * AS_STRIDE + ks * 8 + q + 4]);
            }
#pragma unroll
            for (int nf = 0; nf < NF; nf++) {
                int c = warpN * (BN / 2) + nf * 8 + g;
                bf[nf][0] = __float_as_uint(Bsb[(ks * 8 + q) * BS_STRIDE + c]);
                bf[nf][1] = __float_as_uint(Bsb[(ks * 8 + q + 4) * BS_STRIDE + c]);
            }
#pragma unroll
            for (int mf = 0; mf < 2; mf++)
#pragma unroll
                for (int nf = 0; nf < NF; nf++)
                    mma_tf32(acc[mf][nf], af[mf], bf[nf]);
        }
    }

    // epilogue: bias -> silu -> +res -> tf32-rounded store
#pragma unroll
    for (int mf = 0; mf < 2; mf++) {
#pragma unroll
        for (int nf = 0; nf < NF; nf++) {
            const int col = col0 + warpN * (BN / 2) + nf * 8 + 2 * q;
            float bv0 = 0.0f, bv1 = 0.0f;
            if (bias) { bv0 = bias[col]; bv1 = bias[col + 1]; }
#pragma unroll
            for (int h = 0; h < 2; h++) {
                const int row = row0 + warpM * 32 + mf * 16 + g + h * 8;
                float v0 = acc[mf][nf][h * 2 + 0] + bv0;
                float v1 = acc[mf][nf][h * 2 + 1] + bv1;
                v0 = silu_f(v0);
                v1 = silu_f(v1);
                const size_t off = (size_t)row * Nfull + col;
                if (res) {
                    float2 r = *reinterpret_cast<const float2*>(res + off);
                    v0 += r.x; v1 += r.y;
                }
                uint2 o;
                o.x = tf32r(v0);
                o.y = tf32r(v1);
                *reinterpret_cast<uint2*>(C + off) = o;
            }
        }
    }
}

static constexpr int mma_smem(int BN) {
    return 3 * (128 * 20 + 16 * (BN + 4)) * 4;
}

// ---------------- round fp32 -> tf32-representable fp32 ----------------
__global__ void round_copy_kernel(const float4* __restrict__ in, float4* __restrict__ out, int n4)
{
    int i = blockIdx.x * blockDim.x + threadIdx.x;
    int stride = gridDim.x * blockDim.x;
    for (; i < n4; i += stride) {
        float4 v = in[i];
        uint4 o;
        o.x = tf32r(v.x); o.y = tf32r(v.y); o.z = tf32r(v.z); o.w = tf32r(v.w);
        *reinterpret_cast<uint4*>(&out[i]) = o;
    }
}

// ---------------- rbf gating: xkj[r,:] *= (rbf[r,:] @ W1) @ W2 ; tf32-rounded ----------------
__global__ void rbf_gate_kernel(float* __restrict__ xkj,
                                const float* __restrict__ rbf,
                                const float* __restrict__ W1,   // [6,8]
                                const float* __restrict__ W2)   // [8,256]
{
    __shared__ __align__(16) float sW2[BAS * H_DIM];
    __shared__ float sW1[NR * BAS];
    for (int i = threadIdx.x; i < BAS * H_DIM; i += blockDim.x) sW2[i] = W2[i];
    for (int i = threadIdx.x; i < NR * BAS; i += blockDim.x)    sW1[i] = W1[i];
    __syncthreads();

    const int lane  = threadIdx.x & 31;
    const int wglob = (blockIdx.x * blockDim.x + threadIdx.x) >> 5;
    const int nwarp = (gridDim.x * blockDim.x) >> 5;
    const int j = lane & 7;
    const int g = lane >> 3;

    for (int r = wglob; r < E_EDGES; r += nwarp) {
        float s = 0.f;
        for (int i = g; i < NR; i += 4) s += rbf[(size_t)r * NR + i] * sW1[i * BAS + j];
        s += __shfl_xor_sync(0xffffffffu, s, 8);
        s += __shfl_xor_sync(0xffffffffu, s, 16);
        int c = lane * 8;
        float4 g0 = make_float4(0, 0, 0, 0), g1 = make_float4(0, 0, 0, 0);
#pragma unroll
        for (int jj = 0; jj < BAS; jj++) {
            float sj = __shfl_sync(0xffffffffu, s, jj);
            float4 w0 = *reinterpret_cast<const float4*>(&sW2[jj * H_DIM + c]);
            float4 w1 = *reinterpret_cast<const float4*>(&sW2[jj * H_DIM + c + 4]);
            g0.x += sj * w0.x; g0.y += sj * w0.y; g0.z += sj * w0.z; g0.w += sj * w0.w;
            g1.x += sj * w1.x; g1.y += sj * w1.y; g1.z += sj * w1.z; g1.w += sj * w1.w;
        }
        float4* p0 = reinterpret_cast<float4*>(&xkj[(size_t)r * H_DIM + c]);
        float4* p1 = reinterpret_cast<float4*>(&xkj[(size_t)r * H_DIM + c + 4]);
        float4 x0 = *p0, x1 = *p1;
        uint4 o0, o1;
        o0.x = tf32r(x0.x * g0.x); o0.y = tf32r(x0.y * g0.y);
        o0.z = tf32r(x0.z * g0.z); o0.w = tf32r(x0.w * g0.w);
        o1.x = tf32r(x1.x * g1.x); o1.y = tf32r(x1.y * g1.y);
        o1.z = tf32r(x1.z * g1.z); o1.w = tf32r(x1.w * g1.w);
        *reinterpret_cast<uint4*>(p0) = o0;
        *reinterpret_cast<uint4*>(p1) = o1;
    }
}

// ---------------- zero scratch ----------------
__global__ void zero_kernel(float4* __restrict__ p, int n4)
{
    int i = blockIdx.x * blockDim.x + threadIdx.x;
    int stride = gridDim.x * blockDim.x;
    for (; i < n4; i += stride) p[i] = make_float4(0, 0, 0, 0);
}

// ---------------- triplet pass ----------------
__global__ void triplet_kernel(const float* __restrict__ sbf,
                               const int* __restrict__ idx_kj,
                               const int* __restrict__ idx_ji,
                               const float* __restrict__ W1,   // [42,8]
                               const float* __restrict__ W2,   // [8,64]
                               const float* __restrict__ xkjd, // [E,64]
                               float* __restrict__ agg)        // [E,64]
{
    __shared__ float sW1[NSR * BAS];
    __shared__ __align__(16) float sW2[BAS * I_DIM];
    for (int i = threadIdx.x; i < NSR * BAS; i += blockDim.x) sW1[i] = W1[i];
    for (int i = threadIdx.x; i < BAS * I_DIM; i += blockDim.x) sW2[i] = W2[i];
    __syncthreads();

    const int lane  = threadIdx.x & 31;
    const int wglob = (blockIdx.x * blockDim.x + threadIdx.x) >> 5;
    const int nwarp = (gridDim.x * blockDim.x) >> 5;
    const int sub = lane >> 4;
    const int sl  = lane & 15;
    const int j   = sl & 7;
    const int g   = sl >> 3;

    for (int p = wglob; p * 2 < T_TRIP; p += nwarp) {
        int t = p * 2 + sub;
        const float* srow = sbf + (size_t)t * NSR;
        float s = 0.f;
        for (int i = g; i < NSR; i += 2) s += srow[i] * sW1[i * BAS + j];
        s += __shfl_xor_sync(0xffffffffu, s, 8);

        int ekj = idx_kj[t];
        int eji = idx_ji[t];
        int c = sl * 4;
        float4 xv = *reinterpret_cast<const float4*>(&xkjd[(size_t)ekj * I_DIM + c]);
        float4 m = make_float4(0, 0, 0, 0);
#pragma unroll
        for (int jj = 0; jj < BAS; jj++) {
            float sj = __shfl_sync(0xffffffffu, s, (sub << 4) + jj);
            float4 w = *reinterpret_cast<const float4*>(&sW2[jj * I_DIM + c]);
            m.x += sj * w.x; m.y += sj * w.y; m.z += sj * w.z; m.w += sj * w.w;
        }
        m.x *= xv.x; m.y *= xv.y; m.z *= xv.z; m.w *= xv.w;
        atomicAdd(reinterpret_cast<float4*>(&agg[(size_t)eji * I_DIM + c]), m);
    }
}

// ---------------- launch ----------------
extern "C" void kernel_launch(void* const* d_in, const int* in_sizes, int n_in,
                              void* d_out, int out_size)
{
    const float* x      = (const float*)d_in[0];
    const float* rbf    = (const float*)d_in[1];
    const float* sbf    = (const float*)d_in[2];
    const int*   idx_kj = (const int*)d_in[3];
    const int*   idx_ji = (const int*)d_in[4];
    const float* W_ji   = (const float*)d_in[5];
    const float* b_ji   = (const float*)d_in[6];
    const float* W_kj   = (const float*)d_in[7];
    const float* b_kj   = (const float*)d_in[8];
    const float* W_rbf1 = (const float*)d_in[9];
    const float* W_rbf2 = (const float*)d_in[10];
    const float* W_sbf1 = (const float*)d_in[11];
    const float* W_sbf2 = (const float*)d_in[12];
    const float* W_down = (const float*)d_in[13];
    const float* W_up   = (const float*)d_in[14];
    const float* Wb1_1  = (const float*)d_in[15];
    const float* bb1_1  = (const float*)d_in[16];
    const float* Wb1_2  = (const float*)d_in[17];
    const float* bb1_2  = (const float*)d_in[18];
    const float* W_lin  = (const float*)d_in[19];
    const float* b_lin  = (const float*)d_in[20];
    const float* Wa1_1  = (const float*)d_in[21];
    const float* ba1_1  = (const float*)d_in[22];
    const float* Wa1_2  = (const float*)d_in[23];
    const float* ba1_2  = (const float*)d_in[24];
    const float* Wa2_1  = (const float*)d_in[25];
    const float* ba2_1  = (const float*)d_in[26];
    const float* Wa2_2  = (const float*)d_in[27];
    const float* ba2_2  = (const float*)d_in[28];
    float* out = (float*)d_out;

    float *xr, *xji, *bufA, *bufB, *xkjd, *agg, *wr;
    cudaGetSymbolAddress((void**)&xr,   g_xr);
    cudaGetSymbolAddress((void**)&xji,  g_xji);
    cudaGetSymbolAddress((void**)&bufA, g_bufA);
    cudaGetSymbolAddress((void**)&bufB, g_bufB);
    cudaGetSymbolAddress((void**)&xkjd, g_xkjd);
    cudaGetSymbolAddress((void**)&agg,  g_agg);
    cudaGetSymbolAddress((void**)&wr,   g_wr);

    constexpr int SM_BIG  = mma_smem(128);   // ~56 KB
    constexpr int SM_DOWN = mma_smem(64);
    cudaFuncSetAttribute(mma_gemm<128, 256>, cudaFuncAttributeMaxDynamicSharedMemorySize, SM_BIG);
    cudaFuncSetAttribute(mma_gemm<64, 256>,  cudaFuncAttributeMaxDynamicSharedMemorySize, SM_DOWN);
    cudaFuncSetAttribute(mma_gemm<128, 64>,  cudaFuncAttributeMaxDynamicSharedMemorySize, SM_BIG);

    // pre-round activations + weights to tf32-representable fp32 (unbiased MMA)
    round_copy_kernel<<<1024, 256>>>((const float4*)x, (float4*)xr, E_EDGES * H_DIM / 4);
    round_copy_kernel<<<64, 256>>>((const float4*)W_ji,  (float4*)(wr + WO_JI),   16384);
    round_copy_kernel<<<64, 256>>>((const float4*)W_kj,  (float4*)(wr + WO_KJ),   16384);
    round_copy_kernel<<<64, 256>>>((const float4*)Wb1_1, (float4*)(wr + WO_B11),  16384);
    round_copy_kernel<<<64, 256>>>((const float4*)Wb1_2, (float4*)(wr + WO_B12),  16384);
    round_copy_kernel<<<64, 256>>>((const float4*)W_lin, (float4*)(wr + WO_LIN),  16384);
    round_copy_kernel<<<64, 256>>>((const float4*)Wa1_1, (float4*)(wr + WO_A11),  16384);
    round_copy_kernel<<<64, 256>>>((const float4*)Wa1_2, (float4*)(wr + WO_A12),  16384);
    round_copy_kernel<<<64, 256>>>((const float4*)Wa2_1, (float4*)(wr + WO_A21),  16384);
    round_copy_kernel<<<64, 256>>>((const float4*)Wa2_2, (float4*)(wr + WO_A22),  16384);
    round_copy_kernel<<<16, 256>>>((const float4*)W_down, (float4*)(wr + WO_DOWN), 4096);
    round_copy_kernel<<<16, 256>>>((const float4*)W_up,   (float4*)(wr + WO_UP),   4096);

    const dim3 gBig(E_EDGES / 128, H_DIM / 128);   // (1024, 2)
    const dim3 gDown(E_EDGES / 128, 1);

    // x_ji = silu(x@W_ji + b); x_kj = silu(x@W_kj + b)
    mma_gemm<128, 256><<<gBig, 256, SM_BIG>>>(xr, wr + WO_JI, b_ji, nullptr, xji, H_DIM);
    mma_gemm<128, 256><<<gBig, 256, SM_BIG>>>(xr, wr + WO_KJ, b_kj, nullptr, bufA, H_DIM);
    rbf_gate_kernel<<<2048, 256>>>(bufA, rbf, W_rbf1, W_rbf2);
    // x_kj_down = silu((x_kj*g) @ W_down)
    mma_gemm<64, 256><<<gDown, 256, SM_DOWN>>>(bufA, wr + WO_DOWN, nullptr, nullptr, xkjd, I_DIM);

    // triplet message passing
    zero_kernel<<<1024, 256>>>((float4*)agg, E_EDGES * I_DIM / 4);
    triplet_kernel<<<2048, 256>>>(sbf, idx_kj, idx_ji, W_sbf1, W_sbf2, xkjd, agg);

    // h = x_ji + silu(agg @ W_up)
    mma_gemm<128, 64><<<gBig, 256, SM_BIG>>>(agg, wr + WO_UP, nullptr, xji, bufA, H_DIM);

    // pre-skip residual block
    mma_gemm<128, 256><<<gBig, 256, SM_BIG>>>(bufA, wr + WO_B11, bb1_1, nullptr, bufB, H_DIM);
    mma_gemm<128, 256><<<gBig, 256, SM_BIG>>>(bufB, wr + WO_B12, bb1_2, bufA, bufA, H_DIM);
    // skip: h = silu(h@W_lin+b) + x
    mma_gemm<128, 256><<<gBig, 256, SM_BIG>>>(bufA, wr + WO_LIN, b_lin, x, bufB, H_DIM);
    // post-skip residual blocks
    mma_gemm<128, 256><<<gBig, 256, SM_BIG>>>(bufB, wr + WO_A11, ba1_1, nullptr, bufA, H_DIM);
    mma_gemm<128, 256><<<gBig, 256, SM_BIG>>>(bufA, wr + WO_A12, ba1_2, bufB, bufB, H_DIM);
    mma_gemm<128, 256><<<gBig, 256, SM_BIG>>>(bufB, wr + WO_A21, ba2_1, nullptr, bufA, H_DIM);
    mma_gemm<128, 256><<<gBig, 256, SM_BIG>>>(bufA, wr + WO_A22, ba2_2, bufB, out, H_DIM);
}